// round 11
// baseline (speedup 1.0000x reference)
#include <cuda_runtime.h>
#include <cstdint>

#define Bp 400
#define Np 8000
#define Dp 100
#define SCALERp 4

#define TILE 4
#define WARPS 8
#define THREADS 256
#define ROWS_PER_BLOCK 1600
#define BLOCKS_PER_B (Np / ROWS_PER_BLOCK)     // 5
#define TOTAL_BLOCKS (Bp * BLOCKS_PER_B)       // 2000

#define STAGE_ROWS 64
#define STAGE_BYTES (STAGE_ROWS * Dp * 4)      // 25600
#define NSTAGES 3
#define STAGES_PER_BLOCK (ROWS_PER_BLOCK / STAGE_ROWS)   // 25
#define SUBTILES 2                              // per warp per stage (8 rows)

#define RSTRIDE 28
#define BUFROWS 8

// Dynamic smem layout
#define OFF_RED   (NSTAGES * STAGE_BYTES)                    // 76800
#define RED_BYTES (WARPS * BUFROWS * RSTRIDE * 4)            // 7168
#define OFF_ACC   (OFF_RED + RED_BYTES)                      // 83968
#define ACC_BYTES (WARPS * Dp * 4)                           // 3200
#define OFF_MBAR  (OFF_ACC + ACC_BYTES)                      // 87168
#define SMEM_TOTAL (OFF_MBAR + 64)                           // 87232

__device__ float g_partial[Bp * BLOCKS_PER_B * Dp];
__device__ int   g_cnt = 0;

__device__ __forceinline__ float tanh_approx(float x) {
    float y;
    asm("tanh.approx.f32 %0, %1;" : "=f"(y) : "f"(x));
    return y;
}
__device__ __forceinline__ uint32_t sm32(const void* p) {
    uint32_t a;
    asm("{ .reg .u64 t; cvta.to.shared.u64 t, %1; cvt.u32.u64 %0, t; }"
        : "=r"(a) : "l"(p));
    return a;
}
#define MBAR_INIT(addr, cnt) \
    asm volatile("mbarrier.init.shared.b64 [%0], %1;" :: "r"(addr), "r"(cnt) : "memory")
#define MBAR_EXPECT_TX(addr, bytes) \
    asm volatile("mbarrier.arrive.expect_tx.shared.b64 _, [%0], %1;" :: "r"(addr), "r"(bytes) : "memory")
#define MBAR_ARRIVE(addr) \
    asm volatile("mbarrier.arrive.shared.b64 _, [%0];" :: "r"(addr) : "memory")
#define MBAR_WAIT(addr, parity) do {                                        \
    asm volatile(                                                            \
        "{\n\t.reg .pred P;\n\t"                                             \
        "W%=:\n\t"                                                           \
        "mbarrier.try_wait.parity.acquire.cta.shared::cta.b64 P, [%0], %1, 0x989680;\n\t" \
        "@P bra.uni D%=;\n\t"                                                \
        "bra.uni W%=;\n\t"                                                   \
        "D%=:\n\t}"                                                          \
        :: "r"(addr), "r"(parity) : "memory");                               \
} while (0)
#define BULK_G2S(dst, src, bytes, mbar) \
    asm volatile("cp.async.bulk.shared::cta.global.mbarrier::complete_tx::bytes " \
                 "[%0], [%1], %2, [%3];" \
                 :: "r"(dst), "l"(src), "r"(bytes), "r"(mbar) : "memory")

__global__ __launch_bounds__(THREADS)
void fused_pass_kernel(const float* __restrict__ x,
                       const float* __restrict__ x_scaler,
                       const float* __restrict__ dim_weight,
                       const float* __restrict__ w,
                       float* __restrict__ out_small,
                       float* __restrict__ alpha_out,
                       float* __restrict__ beta_out)
{
    extern __shared__ __align__(128) char dsm[];
    __shared__ int s_last;

    const int b    = blockIdx.x / BLOCKS_PER_B;
    const int c    = blockIdx.x % BLOCKS_PER_B;
    const int warp = threadIdx.x >> 5;
    const int lane = threadIdx.x & 31;
    const int tid  = threadIdx.x;

    const uint32_t smb   = sm32(dsm);
    const uint32_t mfull = smb + OFF_MBAR;           // full[s] at +8s
    const uint32_t mempty= smb + OFF_MBAR + 24;      // empty[s] at +8s
    float* red = reinterpret_cast<float*>(dsm + OFF_RED) + warp * (BUFROWS * RSTRIDE);
    float* sacc= reinterpret_cast<float*>(dsm + OFF_ACC);

    const long long rowbase = (long long)b * Np;
    const float* gsrc_base = x + (rowbase + (long long)c * ROWS_PER_BLOCK) * Dp;

    if (tid == 0) {
        #pragma unroll
        for (int s = 0; s < NSTAGES; s++) {
            MBAR_INIT(mfull + 8 * s, 1);
            MBAR_INIT(mempty + 8 * s, WARPS);
        }
    }
    __syncthreads();

    // Prologue: fill all stages
    if (tid == 0) {
        #pragma unroll
        for (int s = 0; s < NSTAGES; s++) {
            MBAR_EXPECT_TX(mfull + 8 * s, STAGE_BYTES);
            BULK_G2S(smb + s * STAGE_BYTES,
                     gsrc_base + (long long)s * STAGE_ROWS * Dp,
                     STAGE_BYTES, mfull + 8 * s);
        }
    }

    // Per-lane weight slices
    float4 dw4 = make_float4(0.f, 0.f, 0.f, 0.f);
    float4 w14 = make_float4(0.f, 0.f, 0.f, 0.f);
    if (lane < 25) {
        dw4 = *reinterpret_cast<const float4*>(dim_weight + 4 * lane);
        w14.x = w[(4 * lane + 0) * 2 + 1];
        w14.y = w[(4 * lane + 1) * 2 + 1];
        w14.z = w[(4 * lane + 2) * 2 + 1];
        w14.w = w[(4 * lane + 3) * 2 + 1];
    }
    const bool redlane = (lane < 4) | ((lane >= 16) & (lane < 20));
    const int  redrow  = (lane < 4) ? lane : (lane - 12);

    float4 acc = make_float4(0.f, 0.f, 0.f, 0.f);

    for (int t = 0; t < STAGES_PER_BLOCK; t++) {
        const int slot = t % NSTAGES;
        const int k    = t / NSTAGES;
        MBAR_WAIT(mfull + 8 * slot, k & 1);

        const char* stage = dsm + slot * STAGE_BYTES;

        #pragma unroll
        for (int sub = 0; sub < SUBTILES; sub++) {
            const int rloc = warp * (TILE * SUBTILES) + sub * TILE;   // row in stage
            const int n0   = c * ROWS_PER_BLOCK + t * STAGE_ROWS + rloc;

            // Load 4 rows from smem stage into registers
            float4 v[TILE];
            if (lane < 25) {
                #pragma unroll
                for (int r = 0; r < TILE; r++)
                    v[r] = *reinterpret_cast<const float4*>(
                        stage + (rloc + r) * (Dp * 4) + lane * 16);
                #pragma unroll
                for (int r = 0; r < TILE; r++) {
                    const float4 q = v[r];
                    red[r * RSTRIDE + lane] =
                        (q.x * dw4.x + q.y * dw4.y) + (q.z * dw4.z + q.w * dw4.w);
                    red[(r + TILE) * RSTRIDE + lane] =
                        (q.x * w14.x + q.y * w14.y) + (q.z * w14.z + q.w * w14.w);
                }
            }
            __syncwarp();

            float sum = 0.f;
            if (redlane) {
                const float4* row = reinterpret_cast<const float4*>(red + redrow * RSTRIDE);
                float4 s4 = row[0];
                #pragma unroll
                for (int l = 1; l < 6; l++) {
                    const float4 q = row[l];
                    s4.x += q.x; s4.y += q.y; s4.z += q.z; s4.w += q.w;
                }
                sum = ((s4.x + s4.y) + (s4.z + s4.w)) + red[redrow * RSTRIDE + 24];
            }
            const float a = tanh_approx(sum);
            if (lane < 4)
                alpha_out[rowbase + n0 + lane] = a;
            else if (redlane)
                beta_out[rowbase + n0 + (lane - 16)] = sum;

            // Pooled accumulation; first shfl is the warp convergence point
            #pragma unroll
            for (int r = 0; r < TILE; r++) {
                const float ar = __shfl_sync(0xffffffffu, a, r);
                const float4 q = v[r];
                acc.x += ar * q.x;
                acc.y += ar * q.y;
                acc.z += ar * q.z;
                acc.w += ar * q.w;
            }
        }

        if (lane == 0) MBAR_ARRIVE(mempty + 8 * slot);

        // Producer: refill this slot once all 8 warps released it
        if (tid == 0 && t + NSTAGES < STAGES_PER_BLOCK) {
            MBAR_WAIT(mempty + 8 * slot, k & 1);
            MBAR_EXPECT_TX(mfull + 8 * slot, STAGE_BYTES);
            BULK_G2S(smb + slot * STAGE_BYTES,
                     gsrc_base + (long long)(t + NSTAGES) * STAGE_ROWS * Dp,
                     STAGE_BYTES, mfull + 8 * slot);
        }
    }

    // ---- Block-reduce the 8 warp accumulators (deterministic)
    if (lane < 25) {
        sacc[warp * Dp + lane * 4 + 0] = acc.x;
        sacc[warp * Dp + lane * 4 + 1] = acc.y;
        sacc[warp * Dp + lane * 4 + 2] = acc.z;
        sacc[warp * Dp + lane * 4 + 3] = acc.w;
    }
    __syncthreads();
    for (int d = tid; d < Dp; d += THREADS) {
        float sum = 0.f;
        #pragma unroll
        for (int wp = 0; wp < WARPS; wp++) sum += sacc[wp * Dp + d];
        g_partial[((long long)b * BLOCKS_PER_B + c) * Dp + d] = sum;
    }

    // ---- Last-arriving block computes the [B,2] head (deterministic)
    __threadfence();
    if (tid == 0) {
        int old = atomicAdd(&g_cnt, 1);
        s_last = (old == TOTAL_BLOCKS - 1) ? 1 : 0;
    }
    __syncthreads();
    if (!s_last) return;
    if (tid == 0) g_cnt = 0;

    for (int b2 = warp; b2 < Bp; b2 += WARPS) {
        float4 f4 = make_float4(0.f, 0.f, 0.f, 0.f);
        if (lane < 25) {
            #pragma unroll
            for (int cc = 0; cc < BLOCKS_PER_B; cc++) {
                const float4 g = *reinterpret_cast<const float4*>(
                    g_partial + ((long long)b2 * BLOCKS_PER_B + cc) * Dp + 4 * lane);
                f4.x += g.x; f4.y += g.y; f4.z += g.z; f4.w += g.w;
            }
        }
        float p0 = 0.f, p1 = 0.f;
        if (lane < 25) {
            p0 = f4.x * w[(4*lane+0)*2+0] + f4.y * w[(4*lane+1)*2+0]
               + f4.z * w[(4*lane+2)*2+0] + f4.w * w[(4*lane+3)*2+0];
            p1 = f4.x * w[(4*lane+0)*2+1] + f4.y * w[(4*lane+1)*2+1]
               + f4.z * w[(4*lane+2)*2+1] + f4.w * w[(4*lane+3)*2+1];
        }
        #pragma unroll
        for (int off = 16; off; off >>= 1) {
            p0 += __shfl_xor_sync(0xffffffffu, p0, off);
            p1 += __shfl_xor_sync(0xffffffffu, p1, off);
        }
        if (lane == 0) {
            #pragma unroll
            for (int s = 0; s < SCALERp; s++) {
                const float xs = x_scaler[b2 * SCALERp + s];
                p0 += xs * w[(Dp + s) * 2 + 0];
                p1 += xs * w[(Dp + s) * 2 + 1];
            }
            out_small[b2 * 2 + 0] = p0;
            out_small[b2 * 2 + 1] = p1;
        }
    }
}

extern "C" void kernel_launch(void* const* d_in, const int* in_sizes, int n_in,
                              void* d_out, int out_size)
{
    const float* x          = (const float*)d_in[0];
    const float* x_scaler   = (const float*)d_in[1];
    const float* dim_weight = (const float*)d_in[2];
    const float* w          = (const float*)d_in[3];

    float* out_base  = (float*)d_out;
    float* out_small = out_base;                       // 800 floats
    float* alpha     = out_base + Bp * 2;              // [B,1,N]
    float* beta      = alpha + (long long)Bp * Np;     // [B,N]

    cudaFuncSetAttribute(fused_pass_kernel,
                         cudaFuncAttributeMaxDynamicSharedMemorySize, SMEM_TOTAL);
    fused_pass_kernel<<<TOTAL_BLOCKS, THREADS, SMEM_TOTAL>>>(
        x, x_scaler, dim_weight, w, out_small, alpha, beta);
}

// round 12
// speedup vs baseline: 1.1199x; 1.1199x over previous
#include <cuda_runtime.h>
#include <cstdint>

#define Bp 400
#define Np 8000
#define Dp 100
#define SCALERp 4

#define TILE 4
#define CWARPS 8            // compute warps (0-3 LDG, 4-7 TMA consumers)
#define THREADS 288         // + 1 producer warp (warp 8)
#define ROWS_PER_BLOCK 1600
#define BLOCKS_PER_B (Np / ROWS_PER_BLOCK)   // 5
#define TOTAL_BLOCKS (Bp * BLOCKS_PER_B)     // 2000

// LDG half: rows [0,800) of the unit; warp w owns rows [w*200, w*200+200)
#define LDG_TILES 50
// TMA half: rows [800,1600); 25 stages x 32 rows, ring of 3
#define STAGE_ROWS 32
#define STAGE_BYTES (STAGE_ROWS * Dp * 4)    // 12800
#define NST 3
#define NSTAGES_TOTAL 25
#define SUBTILES 2                           // 8 rows per consumer warp per stage

#define RSTRIDE 28
#define BUFROWS 8

// Dynamic smem layout
#define OFF_RED   (NST * STAGE_BYTES)                     // 38400
#define RED_BYTES (CWARPS * BUFROWS * RSTRIDE * 4)        // 7168
#define OFF_ACC   (OFF_RED + RED_BYTES)                   // 45568
#define ACC_BYTES (CWARPS * Dp * 4)                       // 3200
#define OFF_MBAR  (OFF_ACC + ACC_BYTES)                   // 48768
#define SMEM_TOTAL (OFF_MBAR + 64)

__device__ float g_partial[Bp * BLOCKS_PER_B * Dp];
__device__ int   g_cnt = 0;

__device__ __forceinline__ float tanh_approx(float x) {
    float y;
    asm("tanh.approx.f32 %0, %1;" : "=f"(y) : "f"(x));
    return y;
}
__device__ __forceinline__ uint32_t sm32(const void* p) {
    uint32_t a;
    asm("{ .reg .u64 t; cvta.to.shared.u64 t, %1; cvt.u32.u64 %0, t; }"
        : "=r"(a) : "l"(p));
    return a;
}
#define MBAR_INIT(addr, cnt) \
    asm volatile("mbarrier.init.shared.b64 [%0], %1;" :: "r"(addr), "r"(cnt) : "memory")
#define MBAR_EXPECT_TX(addr, bytes) \
    asm volatile("mbarrier.arrive.expect_tx.shared.b64 _, [%0], %1;" :: "r"(addr), "r"(bytes) : "memory")
#define MBAR_ARRIVE(addr) \
    asm volatile("mbarrier.arrive.shared.b64 _, [%0];" :: "r"(addr) : "memory")
#define MBAR_WAIT(addr, parity) do {                                        \
    asm volatile(                                                            \
        "{\n\t.reg .pred P;\n\t"                                             \
        "W%=:\n\t"                                                           \
        "mbarrier.try_wait.parity.acquire.cta.shared::cta.b64 P, [%0], %1, 0x989680;\n\t" \
        "@P bra.uni D%=;\n\t"                                                \
        "bra.uni W%=;\n\t"                                                   \
        "D%=:\n\t}"                                                          \
        :: "r"(addr), "r"(parity) : "memory");                               \
} while (0)
#define BULK_G2S(dst, src, bytes, mbar) \
    asm volatile("cp.async.bulk.shared::cta.global.mbarrier::complete_tx::bytes " \
                 "[%0], [%1], %2, [%3];" \
                 :: "r"(dst), "l"(src), "r"(bytes), "r"(mbar) : "memory")

// Shared 4-row compute core (identical to the proven R10 path)
__device__ __forceinline__ void tile4_compute(
    const float4 v[TILE], long long out_idx,   // rowbase + n0
    int lane, bool redlane, int redrow,
    const float4 dw4, const float4 w14,
    float* __restrict__ red, float4& acc,
    float* __restrict__ alpha_out, float* __restrict__ beta_out)
{
    if (lane < 25) {
        #pragma unroll
        for (int r = 0; r < TILE; r++) {
            const float4 q = v[r];
            red[r * RSTRIDE + lane] =
                (q.x * dw4.x + q.y * dw4.y) + (q.z * dw4.z + q.w * dw4.w);
            red[(r + TILE) * RSTRIDE + lane] =
                (q.x * w14.x + q.y * w14.y) + (q.z * w14.z + q.w * w14.w);
        }
    }
    __syncwarp();
    float sum = 0.f;
    if (redlane) {
        const float4* row = reinterpret_cast<const float4*>(red + redrow * RSTRIDE);
        float4 s4 = row[0];
        #pragma unroll
        for (int l = 1; l < 6; l++) {
            const float4 q = row[l];
            s4.x += q.x; s4.y += q.y; s4.z += q.z; s4.w += q.w;
        }
        sum = ((s4.x + s4.y) + (s4.z + s4.w)) + red[redrow * RSTRIDE + 24];
    }
    const float a = tanh_approx(sum);
    if (lane < 4)
        alpha_out[out_idx + lane] = a;
    else if (redlane)
        beta_out[out_idx + (lane - 16)] = sum;
    #pragma unroll
    for (int r = 0; r < TILE; r++) {
        const float ar = __shfl_sync(0xffffffffu, a, r);
        const float4 q = v[r];
        acc.x += ar * q.x;
        acc.y += ar * q.y;
        acc.z += ar * q.z;
        acc.w += ar * q.w;
    }
}

__global__ __launch_bounds__(THREADS, 3)
void fused_pass_kernel(const float* __restrict__ x,
                       const float* __restrict__ x_scaler,
                       const float* __restrict__ dim_weight,
                       const float* __restrict__ w,
                       float* __restrict__ out_small,
                       float* __restrict__ alpha_out,
                       float* __restrict__ beta_out)
{
    extern __shared__ __align__(128) char dsm[];
    __shared__ int s_last;

    const int b    = blockIdx.x / BLOCKS_PER_B;
    const int c    = blockIdx.x % BLOCKS_PER_B;
    const int warp = threadIdx.x >> 5;
    const int lane = threadIdx.x & 31;
    const int tid  = threadIdx.x;

    const uint32_t smb    = sm32(dsm);
    const uint32_t mfull  = smb + OFF_MBAR;        // full[s]  at +8s
    const uint32_t mempty = smb + OFF_MBAR + 24;   // empty[s] at +8s
    float* red  = reinterpret_cast<float*>(dsm + OFF_RED)
                  + (warp < CWARPS ? warp : 0) * (BUFROWS * RSTRIDE);
    float* sacc = reinterpret_cast<float*>(dsm + OFF_ACC);

    const long long rowbase = (long long)b * Np;
    const int unit0 = c * ROWS_PER_BLOCK;

    if (tid == 0) {
        #pragma unroll
        for (int s = 0; s < NST; s++) {
            MBAR_INIT(mfull + 8 * s, 1);
            MBAR_INIT(mempty + 8 * s, 4);   // 4 consumer warps release each slot
        }
    }
    __syncthreads();

    // Per-lane weight slices
    float4 dw4 = make_float4(0.f, 0.f, 0.f, 0.f);
    float4 w14 = make_float4(0.f, 0.f, 0.f, 0.f);
    if (lane < 25) {
        dw4 = *reinterpret_cast<const float4*>(dim_weight + 4 * lane);
        w14.x = w[(4 * lane + 0) * 2 + 1];
        w14.y = w[(4 * lane + 1) * 2 + 1];
        w14.z = w[(4 * lane + 2) * 2 + 1];
        w14.w = w[(4 * lane + 3) * 2 + 1];
    }
    const bool redlane = (lane < 4) | ((lane >= 16) & (lane < 20));
    const int  redrow  = (lane < 4) ? lane : (lane - 12);

    float4 acc = make_float4(0.f, 0.f, 0.f, 0.f);

    if (warp >= CWARPS) {
        // ---------------- Producer warp (TMA bulk ring) ----------------
        if (lane == 0) {
            const float* gsrc = x + (rowbase + unit0 + 800) * Dp;
            for (int s = 0; s < NSTAGES_TOTAL; s++) {
                const int slot = s % NST;
                if (s >= NST) MBAR_WAIT(mempty + 8 * slot, ((s / NST) - 1) & 1);
                MBAR_EXPECT_TX(mfull + 8 * slot, STAGE_BYTES);
                BULK_G2S(smb + slot * STAGE_BYTES,
                         gsrc + (long long)s * STAGE_ROWS * Dp,
                         STAGE_BYTES, mfull + 8 * slot);
            }
        }
    } else if (warp < 4) {
        // ---------------- LDG path: rows [warp*200, warp*200+200) ------
        const float4* base4 = reinterpret_cast<const float4*>(
            x + (rowbase + unit0 + warp * 200) * Dp);
        float4 v[2][TILE];
        if (lane < 25) {
            #pragma unroll
            for (int r = 0; r < TILE; r++) v[0][r] = base4[r * 25 + lane];
        }
        #pragma unroll 2
        for (int t = 0; t < LDG_TILES; t++) {
            const int cur = t & 1;
            if ((t + 1 < LDG_TILES) & (lane < 25)) {
                const float4* nb = base4 + (t + 1) * (TILE * 25);
                #pragma unroll
                for (int r = 0; r < TILE; r++) v[cur ^ 1][r] = nb[r * 25 + lane];
            }
            tile4_compute(v[cur], rowbase + unit0 + warp * 200 + t * TILE,
                          lane, redlane, redrow, dw4, w14, red, acc,
                          alpha_out, beta_out);
        }
    } else {
        // ---------------- TMA consumer path: warps 4-7 ------------------
        const int cw = warp - 4;
        for (int s = 0; s < NSTAGES_TOTAL; s++) {
            const int slot = s % NST;
            MBAR_WAIT(mfull + 8 * slot, (s / NST) & 1);
            const char* stage = dsm + slot * STAGE_BYTES;
            #pragma unroll
            for (int sub = 0; sub < SUBTILES; sub++) {
                const int rloc = cw * (TILE * SUBTILES) + sub * TILE;
                float4 v[TILE];
                if (lane < 25) {
                    #pragma unroll
                    for (int r = 0; r < TILE; r++)
                        v[r] = *reinterpret_cast<const float4*>(
                            stage + (rloc + r) * (Dp * 4) + lane * 16);
                }
                tile4_compute(v, rowbase + unit0 + 800 + s * STAGE_ROWS + rloc,
                              lane, redlane, redrow, dw4, w14, red, acc,
                              alpha_out, beta_out);
            }
            if (lane == 0) MBAR_ARRIVE(mempty + 8 * slot);
        }
    }

    // ---- Block-reduce the 8 compute-warp accumulators (deterministic)
    if (warp < CWARPS && lane < 25) {
        sacc[warp * Dp + lane * 4 + 0] = acc.x;
        sacc[warp * Dp + lane * 4 + 1] = acc.y;
        sacc[warp * Dp + lane * 4 + 2] = acc.z;
        sacc[warp * Dp + lane * 4 + 3] = acc.w;
    }
    __syncthreads();
    for (int d = tid; d < Dp; d += THREADS) {
        float sum = 0.f;
        #pragma unroll
        for (int wp = 0; wp < CWARPS; wp++) sum += sacc[wp * Dp + d];
        g_partial[((long long)b * BLOCKS_PER_B + c) * Dp + d] = sum;
    }

    // ---- Last-arriving block computes the [B,2] head (deterministic)
    __threadfence();
    if (tid == 0) {
        int old = atomicAdd(&g_cnt, 1);
        s_last = (old == TOTAL_BLOCKS - 1) ? 1 : 0;
    }
    __syncthreads();
    if (!s_last) return;
    if (tid == 0) g_cnt = 0;

    if (warp < CWARPS) {
        for (int b2 = warp; b2 < Bp; b2 += CWARPS) {
            float4 f4 = make_float4(0.f, 0.f, 0.f, 0.f);
            if (lane < 25) {
                #pragma unroll
                for (int cc = 0; cc < BLOCKS_PER_B; cc++) {
                    const float4 g = *reinterpret_cast<const float4*>(
                        g_partial + ((long long)b2 * BLOCKS_PER_B + cc) * Dp + 4 * lane);
                    f4.x += g.x; f4.y += g.y; f4.z += g.z; f4.w += g.w;
                }
            }
            float p0 = 0.f, p1 = 0.f;
            if (lane < 25) {
                p0 = f4.x * w[(4*lane+0)*2+0] + f4.y * w[(4*lane+1)*2+0]
                   + f4.z * w[(4*lane+2)*2+0] + f4.w * w[(4*lane+3)*2+0];
                p1 = f4.x * w[(4*lane+0)*2+1] + f4.y * w[(4*lane+1)*2+1]
                   + f4.z * w[(4*lane+2)*2+1] + f4.w * w[(4*lane+3)*2+1];
            }
            #pragma unroll
            for (int off = 16; off; off >>= 1) {
                p0 += __shfl_xor_sync(0xffffffffu, p0, off);
                p1 += __shfl_xor_sync(0xffffffffu, p1, off);
            }
            if (lane == 0) {
                #pragma unroll
                for (int s = 0; s < SCALERp; s++) {
                    const float xs = x_scaler[b2 * SCALERp + s];
                    p0 += xs * w[(Dp + s) * 2 + 0];
                    p1 += xs * w[(Dp + s) * 2 + 1];
                }
                out_small[b2 * 2 + 0] = p0;
                out_small[b2 * 2 + 1] = p1;
            }
        }
    }
}

extern "C" void kernel_launch(void* const* d_in, const int* in_sizes, int n_in,
                              void* d_out, int out_size)
{
    const float* x          = (const float*)d_in[0];
    const float* x_scaler   = (const float*)d_in[1];
    const float* dim_weight = (const float*)d_in[2];
    const float* w          = (const float*)d_in[3];

    float* out_base  = (float*)d_out;
    float* out_small = out_base;                       // 800 floats
    float* alpha     = out_base + Bp * 2;              // [B,1,N]
    float* beta      = alpha + (long long)Bp * Np;     // [B,N]

    cudaFuncSetAttribute(fused_pass_kernel,
                         cudaFuncAttributeMaxDynamicSharedMemorySize, SMEM_TOTAL);
    fused_pass_kernel<<<TOTAL_BLOCKS, THREADS, SMEM_TOTAL>>>(
        x, x_scaler, dim_weight, w, out_small, alpha, beta);
}

// round 13
// speedup vs baseline: 1.1225x; 1.0023x over previous
#include <cuda_runtime.h>
#include <cstdint>

#define Bp 400
#define Np 8000
#define Dp 100
#define SCALERp 4

#define TILE 4
#define CWARPS 8            // compute warps (0-3 LDG, 4-7 TMA consumers)
#define THREADS 288         // + 1 producer warp (warp 8)
#define ROWS_PER_BLOCK 800
#define BLOCKS_PER_B (Np / ROWS_PER_BLOCK)   // 10
#define TOTAL_BLOCKS (Bp * BLOCKS_PER_B)     // 4000

// LDG half: rows [0,416) of the unit; warp w owns rows [w*104, w*104+104)
#define LDG_ROWS_PER_WARP 104
#define LDG_TILES (LDG_ROWS_PER_WARP / TILE)   // 26
#define LDG_HALF (4 * LDG_ROWS_PER_WARP)       // 416
// TMA half: rows [416,800); 12 stages x 32 rows, ring of 3
#define STAGE_ROWS 32
#define STAGE_BYTES (STAGE_ROWS * Dp * 4)      // 12800
#define NST 3
#define NSTAGES_TOTAL 12
#define SUBTILES 2                             // 8 rows per consumer warp per stage

#define RSTRIDE 28
#define BUFROWS 8

// Dynamic smem layout
#define OFF_RED   (NST * STAGE_BYTES)                     // 38400
#define RED_BYTES (CWARPS * BUFROWS * RSTRIDE * 4)        // 7168
#define OFF_ACC   (OFF_RED + RED_BYTES)                   // 45568
#define ACC_BYTES (CWARPS * Dp * 4)                       // 3200
#define OFF_MBAR  (OFF_ACC + ACC_BYTES)                   // 48768
#define SMEM_TOTAL (OFF_MBAR + 64)

__device__ float g_partial[Bp * BLOCKS_PER_B * Dp];
__device__ int   g_cnt = 0;

__device__ __forceinline__ float tanh_approx(float x) {
    float y;
    asm("tanh.approx.f32 %0, %1;" : "=f"(y) : "f"(x));
    return y;
}
__device__ __forceinline__ uint32_t sm32(const void* p) {
    uint32_t a;
    asm("{ .reg .u64 t; cvta.to.shared.u64 t, %1; cvt.u32.u64 %0, t; }"
        : "=r"(a) : "l"(p));
    return a;
}
#define MBAR_INIT(addr, cnt) \
    asm volatile("mbarrier.init.shared.b64 [%0], %1;" :: "r"(addr), "r"(cnt) : "memory")
#define MBAR_EXPECT_TX(addr, bytes) \
    asm volatile("mbarrier.arrive.expect_tx.shared.b64 _, [%0], %1;" :: "r"(addr), "r"(bytes) : "memory")
#define MBAR_ARRIVE(addr) \
    asm volatile("mbarrier.arrive.shared.b64 _, [%0];" :: "r"(addr) : "memory")
#define MBAR_WAIT(addr, parity) do {                                        \
    asm volatile(                                                            \
        "{\n\t.reg .pred P;\n\t"                                             \
        "W%=:\n\t"                                                           \
        "mbarrier.try_wait.parity.acquire.cta.shared::cta.b64 P, [%0], %1, 0x989680;\n\t" \
        "@P bra.uni D%=;\n\t"                                                \
        "bra.uni W%=;\n\t"                                                   \
        "D%=:\n\t}"                                                          \
        :: "r"(addr), "r"(parity) : "memory");                               \
} while (0)
#define BULK_G2S(dst, src, bytes, mbar) \
    asm volatile("cp.async.bulk.shared::cta.global.mbarrier::complete_tx::bytes " \
                 "[%0], [%1], %2, [%3];" \
                 :: "r"(dst), "l"(src), "r"(bytes), "r"(mbar) : "memory")

// Shared 4-row compute core (proven since R10)
__device__ __forceinline__ void tile4_compute(
    const float4 v[TILE], long long out_idx,   // rowbase + n0
    int lane, bool redlane, int redrow,
    const float4 dw4, const float4 w14,
    float* __restrict__ red, float4& acc,
    float* __restrict__ alpha_out, float* __restrict__ beta_out)
{
    if (lane < 25) {
        #pragma unroll
        for (int r = 0; r < TILE; r++) {
            const float4 q = v[r];
            red[r * RSTRIDE + lane] =
                (q.x * dw4.x + q.y * dw4.y) + (q.z * dw4.z + q.w * dw4.w);
            red[(r + TILE) * RSTRIDE + lane] =
                (q.x * w14.x + q.y * w14.y) + (q.z * w14.z + q.w * w14.w);
        }
    }
    __syncwarp();
    float sum = 0.f;
    if (redlane) {
        const float4* row = reinterpret_cast<const float4*>(red + redrow * RSTRIDE);
        float4 s4 = row[0];
        #pragma unroll
        for (int l = 1; l < 6; l++) {
            const float4 q = row[l];
            s4.x += q.x; s4.y += q.y; s4.z += q.z; s4.w += q.w;
        }
        sum = ((s4.x + s4.y) + (s4.z + s4.w)) + red[redrow * RSTRIDE + 24];
    }
    const float a = tanh_approx(sum);
    if (lane < 4)
        alpha_out[out_idx + lane] = a;
    else if (redlane)
        beta_out[out_idx + (lane - 16)] = sum;
    #pragma unroll
    for (int r = 0; r < TILE; r++) {
        const float ar = __shfl_sync(0xffffffffu, a, r);
        const float4 q = v[r];
        acc.x += ar * q.x;
        acc.y += ar * q.y;
        acc.z += ar * q.z;
        acc.w += ar * q.w;
    }
}

__global__ __launch_bounds__(THREADS, 3)
void fused_pass_kernel(const float* __restrict__ x,
                       const float* __restrict__ x_scaler,
                       const float* __restrict__ dim_weight,
                       const float* __restrict__ w,
                       float* __restrict__ out_small,
                       float* __restrict__ alpha_out,
                       float* __restrict__ beta_out)
{
    extern __shared__ __align__(128) char dsm[];
    __shared__ int s_last;

    const int b    = blockIdx.x / BLOCKS_PER_B;
    const int c    = blockIdx.x % BLOCKS_PER_B;
    const int warp = threadIdx.x >> 5;
    const int lane = threadIdx.x & 31;
    const int tid  = threadIdx.x;

    const uint32_t smb    = sm32(dsm);
    const uint32_t mfull  = smb + OFF_MBAR;        // full[s]  at +8s
    const uint32_t mempty = smb + OFF_MBAR + 24;   // empty[s] at +8s
    float* red  = reinterpret_cast<float*>(dsm + OFF_RED)
                  + (warp < CWARPS ? warp : 0) * (BUFROWS * RSTRIDE);
    float* sacc = reinterpret_cast<float*>(dsm + OFF_ACC);

    const long long rowbase = (long long)b * Np;
    const int unit0 = c * ROWS_PER_BLOCK;

    if (tid == 0) {
        #pragma unroll
        for (int s = 0; s < NST; s++) {
            MBAR_INIT(mfull + 8 * s, 1);
            MBAR_INIT(mempty + 8 * s, 4);   // 4 consumer warps release each slot
        }
    }
    __syncthreads();

    // Per-lane weight slices
    float4 dw4 = make_float4(0.f, 0.f, 0.f, 0.f);
    float4 w14 = make_float4(0.f, 0.f, 0.f, 0.f);
    if (lane < 25) {
        dw4 = *reinterpret_cast<const float4*>(dim_weight + 4 * lane);
        w14.x = w[(4 * lane + 0) * 2 + 1];
        w14.y = w[(4 * lane + 1) * 2 + 1];
        w14.z = w[(4 * lane + 2) * 2 + 1];
        w14.w = w[(4 * lane + 3) * 2 + 1];
    }
    const bool redlane = (lane < 4) | ((lane >= 16) & (lane < 20));
    const int  redrow  = (lane < 4) ? lane : (lane - 12);

    float4 acc = make_float4(0.f, 0.f, 0.f, 0.f);

    if (warp >= CWARPS) {
        // ---------------- Producer warp (TMA bulk ring) ----------------
        if (lane == 0) {
            const float* gsrc = x + (rowbase + unit0 + LDG_HALF) * Dp;
            for (int s = 0; s < NSTAGES_TOTAL; s++) {
                const int slot = s % NST;
                if (s >= NST) MBAR_WAIT(mempty + 8 * slot, ((s / NST) - 1) & 1);
                MBAR_EXPECT_TX(mfull + 8 * slot, STAGE_BYTES);
                BULK_G2S(smb + slot * STAGE_BYTES,
                         gsrc + (long long)s * STAGE_ROWS * Dp,
                         STAGE_BYTES, mfull + 8 * slot);
            }
        }
    } else if (warp < 4) {
        // ------- LDG path: rows [warp*104, warp*104+104) of the unit ----
        const float4* base4 = reinterpret_cast<const float4*>(
            x + (rowbase + unit0 + warp * LDG_ROWS_PER_WARP) * Dp);
        float4 v[2][TILE];
        if (lane < 25) {
            #pragma unroll
            for (int r = 0; r < TILE; r++) v[0][r] = base4[r * 25 + lane];
        }
        #pragma unroll 2
        for (int t = 0; t < LDG_TILES; t++) {
            const int cur = t & 1;
            if ((t + 1 < LDG_TILES) & (lane < 25)) {
                const float4* nb = base4 + (t + 1) * (TILE * 25);
                #pragma unroll
                for (int r = 0; r < TILE; r++) v[cur ^ 1][r] = nb[r * 25 + lane];
            }
            tile4_compute(v[cur],
                          rowbase + unit0 + warp * LDG_ROWS_PER_WARP + t * TILE,
                          lane, redlane, redrow, dw4, w14, red, acc,
                          alpha_out, beta_out);
        }
    } else {
        // ---------------- TMA consumer path: warps 4-7 ------------------
        const int cw = warp - 4;
        for (int s = 0; s < NSTAGES_TOTAL; s++) {
            const int slot = s % NST;
            MBAR_WAIT(mfull + 8 * slot, (s / NST) & 1);
            const char* stage = dsm + slot * STAGE_BYTES;
            #pragma unroll
            for (int sub = 0; sub < SUBTILES; sub++) {
                const int rloc = cw * (TILE * SUBTILES) + sub * TILE;
                float4 v[TILE];
                if (lane < 25) {
                    #pragma unroll
                    for (int r = 0; r < TILE; r++)
                        v[r] = *reinterpret_cast<const float4*>(
                            stage + (rloc + r) * (Dp * 4) + lane * 16);
                }
                tile4_compute(v,
                              rowbase + unit0 + LDG_HALF + s * STAGE_ROWS + rloc,
                              lane, redlane, redrow, dw4, w14, red, acc,
                              alpha_out, beta_out);
            }
            if (lane == 0) MBAR_ARRIVE(mempty + 8 * slot);
        }
    }

    // ---- Block-reduce the 8 compute-warp accumulators (deterministic)
    if (warp < CWARPS && lane < 25) {
        sacc[warp * Dp + lane * 4 + 0] = acc.x;
        sacc[warp * Dp + lane * 4 + 1] = acc.y;
        sacc[warp * Dp + lane * 4 + 2] = acc.z;
        sacc[warp * Dp + lane * 4 + 3] = acc.w;
    }
    __syncthreads();
    for (int d = tid; d < Dp; d += THREADS) {
        float sum = 0.f;
        #pragma unroll
        for (int wp = 0; wp < CWARPS; wp++) sum += sacc[wp * Dp + d];
        g_partial[((long long)b * BLOCKS_PER_B + c) * Dp + d] = sum;
    }

    // ---- Last-arriving block computes the [B,2] head (deterministic)
    __threadfence();
    if (tid == 0) {
        int old = atomicAdd(&g_cnt, 1);
        s_last = (old == TOTAL_BLOCKS - 1) ? 1 : 0;
    }
    __syncthreads();
    if (!s_last) return;
    if (tid == 0) g_cnt = 0;

    if (warp < CWARPS) {
        for (int b2 = warp; b2 < Bp; b2 += CWARPS) {
            float4 f4 = make_float4(0.f, 0.f, 0.f, 0.f);
            if (lane < 25) {
                #pragma unroll
                for (int cc = 0; cc < BLOCKS_PER_B; cc++) {
                    const float4 g = *reinterpret_cast<const float4*>(
                        g_partial + ((long long)b2 * BLOCKS_PER_B + cc) * Dp + 4 * lane);
                    f4.x += g.x; f4.y += g.y; f4.z += g.z; f4.w += g.w;
                }
            }
            float p0 = 0.f, p1 = 0.f;
            if (lane < 25) {
                p0 = f4.x * w[(4*lane+0)*2+0] + f4.y * w[(4*lane+1)*2+0]
                   + f4.z * w[(4*lane+2)*2+0] + f4.w * w[(4*lane+3)*2+0];
                p1 = f4.x * w[(4*lane+0)*2+1] + f4.y * w[(4*lane+1)*2+1]
                   + f4.z * w[(4*lane+2)*2+1] + f4.w * w[(4*lane+3)*2+1];
            }
            #pragma unroll
            for (int off = 16; off; off >>= 1) {
                p0 += __shfl_xor_sync(0xffffffffu, p0, off);
                p1 += __shfl_xor_sync(0xffffffffu, p1, off);
            }
            if (lane == 0) {
                #pragma unroll
                for (int s = 0; s < SCALERp; s++) {
                    const float xs = x_scaler[b2 * SCALERp + s];
                    p0 += xs * w[(Dp + s) * 2 + 0];
                    p1 += xs * w[(Dp + s) * 2 + 1];
                }
                out_small[b2 * 2 + 0] = p0;
                out_small[b2 * 2 + 1] = p1;
            }
        }
    }
}

extern "C" void kernel_launch(void* const* d_in, const int* in_sizes, int n_in,
                              void* d_out, int out_size)
{
    const float* x          = (const float*)d_in[0];
    const float* x_scaler   = (const float*)d_in[1];
    const float* dim_weight = (const float*)d_in[2];
    const float* w          = (const float*)d_in[3];

    float* out_base  = (float*)d_out;
    float* out_small = out_base;                       // 800 floats
    float* alpha     = out_base + Bp * 2;              // [B,1,N]
    float* beta      = alpha + (long long)Bp * Np;     // [B,N]

    cudaFuncSetAttribute(fused_pass_kernel,
                         cudaFuncAttributeMaxDynamicSharedMemorySize, SMEM_TOTAL);
    fused_pass_kernel<<<TOTAL_BLOCKS, THREADS, SMEM_TOTAL>>>(
        x, x_scaler, dim_weight, w, out_small, alpha, beta);
}